// round 6
// baseline (speedup 1.0000x reference)
#include <cuda_runtime.h>
#include <cstdint>

#define BLOCK    256
#define NBLOCKS  1184            // 148 SMs * 8 blocks, full occupancy

__device__ float g_partials[NBLOCKS];
__device__ unsigned int g_count = 0;

__device__ __forceinline__ float4 ldcs4(const float4* p) {
    float4 v;
    asm volatile("ld.global.nc.cs.v4.f32 {%0,%1,%2,%3}, [%4];"
                 : "=f"(v.x), "=f"(v.y), "=f"(v.z), "=f"(v.w) : "l"(p));
    return v;
}

__device__ __forceinline__ float quad_term(float x0, float x2, float x4, float t) {
    const float d = (fabsf(x4 - x2) < 0.1f) ? (x0 - x4) : (x0 - t);
    return fabsf(d);
}

__global__ void __launch_bounds__(BLOCK)
loss_kernel(const float* __restrict__ in,
            const float* __restrict__ tgt,
            long long nrows,
            float* __restrict__ out)
{
    const int tid = threadIdx.x;
    const long long gtid   = (long long)blockIdx.x * BLOCK + tid;
    const long long stride = (long long)gridDim.x * BLOCK;
    const long long nquads = nrows / 4;

    float acc = 0.0f;

    // Tail rows (nrows % 4) — block 0.
    if (blockIdx.x == 0) {
        for (long long r = nquads * 4 + tid; r < nrows; r += BLOCK) {
            acc += quad_term(in[r * 5 + 0], in[r * 5 + 2], in[r * 5 + 4], tgt[r]);
        }
    }

    // Pure register streaming: each iteration handles 4 rows (80B in + 16B tgt).
    #pragma unroll 4
    for (long long q = gtid; q < nquads; q += stride) {
        const float4* __restrict__ p =
            reinterpret_cast<const float4*>(in) + q * 5;
        const float4 v0 = ldcs4(p + 0);
        const float4 v1 = ldcs4(p + 1);
        const float4 v2 = ldcs4(p + 2);
        const float4 v3 = ldcs4(p + 3);
        const float4 v4 = ldcs4(p + 4);
        const float4 t  = ldcs4(reinterpret_cast<const float4*>(tgt) + q);

        // flattened f[j]: row i uses f[5i+0], f[5i+2], f[5i+4]
        acc += quad_term(v0.x, v0.z, v1.x, t.x);   // f0,  f2,  f4
        acc += quad_term(v1.y, v1.w, v2.y, t.y);   // f5,  f7,  f9
        acc += quad_term(v2.z, v3.x, v3.z, t.z);   // f10, f12, f14
        acc += quad_term(v3.w, v4.y, v4.w, t.w);   // f15, f17, f19
    }

    // Warp reduce, then block reduce.
    #pragma unroll
    for (int off = 16; off > 0; off >>= 1)
        acc += __shfl_down_sync(0xFFFFFFFFu, acc, off);

    __shared__ float s_w[BLOCK / 32];
    if ((tid & 31) == 0) s_w[tid >> 5] = acc;
    __syncthreads();

    __shared__ int s_last;
    if (tid == 0) {
        float v = 0.0f;
        #pragma unroll
        for (int w = 0; w < BLOCK / 32; w++) v += s_w[w];
        g_partials[blockIdx.x] = v;
        __threadfence();
        const unsigned int old = atomicAdd(&g_count, 1u);
        s_last = (old == gridDim.x - 1);
    }
    __syncthreads();

    // Last block: deterministic double-precision final reduce.
    if (s_last) {
        __shared__ double sd[BLOCK / 32];
        double a = 0.0;
        for (int i = tid; i < NBLOCKS; i += BLOCK)
            a += (double)g_partials[i];
        #pragma unroll
        for (int off = 16; off > 0; off >>= 1)
            a += __shfl_down_sync(0xFFFFFFFFu, a, off);
        if ((tid & 31) == 0) sd[tid >> 5] = a;
        __syncthreads();
        if (tid == 0) {
            double s = 0.0;
            #pragma unroll
            for (int w = 0; w < BLOCK / 32; w++) s += sd[w];
            out[0] = (float)(s / (double)nrows);
            g_count = 0;    // reset for next graph replay (determinism)
        }
    }
}

extern "C" void kernel_launch(void* const* d_in, const int* in_sizes, int n_in,
                              void* d_out, int out_size)
{
    const float* inputs  = (const float*)d_in[0];   // [N, 5] fp32
    const float* targets = (const float*)d_in[1];   // [N, 1] fp32
    float* out = (float*)d_out;

    const long long nrows = (long long)in_sizes[0] / 5;

    loss_kernel<<<NBLOCKS, BLOCK>>>(inputs, targets, nrows, out);
}

// round 7
// speedup vs baseline: 1.1080x; 1.1080x over previous
#include <cuda_runtime.h>
#include <cstdint>

#define BLOCK   256
#define ROWS    512            // rows per tile; 2560 floats input + 512 targets
#define STAGES  3
#define NBLOCKS 888            // 148 SMs * 6 blocks (36KB smem each)

__device__ float g_partials[NBLOCKS];
__device__ unsigned int g_count = 0;

__device__ __forceinline__ void cp16(uint32_t smem_addr, const void* gptr) {
    asm volatile("cp.async.cg.shared.global.L2::256B [%0], [%1], 16;"
                 :: "r"(smem_addr), "l"(gptr));
}
__device__ __forceinline__ void cp_commit() {
    asm volatile("cp.async.commit_group;");
}
template <int N>
__device__ __forceinline__ void cp_wait() {
    asm volatile("cp.async.wait_group %0;" :: "n"(N));
}

__global__ void __launch_bounds__(BLOCK)
loss_kernel(const float* __restrict__ in,
            const float* __restrict__ tgt,
            long long nrows,
            float* __restrict__ out)
{
    __shared__ __align__(16) float s_in[STAGES][ROWS * 5];
    __shared__ __align__(16) float s_t[STAGES][ROWS];

    const int tid = threadIdx.x;
    const long long fulltiles = nrows / ROWS;
    const long long step = gridDim.x;
    float acc = 0.0f;

    // Tail rows (nrows % ROWS) handled by block 0 directly.
    if (blockIdx.x == 0) {
        for (long long r = fulltiles * ROWS + tid; r < nrows; r += BLOCK) {
            const float x0 = in[r * 5 + 0];
            const float x2 = in[r * 5 + 2];
            const float x4 = in[r * 5 + 4];
            const float t  = tgt[r];
            const float d  = (fabsf(x4 - x2) < 0.1f) ? (x0 - x4) : (x0 - t);
            acc += fabsf(d);
        }
    }

    auto stage = [&](int slot, long long tile) {
        if (tile < fulltiles) {
            const float4* __restrict__ src =
                reinterpret_cast<const float4*>(in + tile * (long long)ROWS * 5);
            const uint32_t sb = (uint32_t)__cvta_generic_to_shared(&s_in[slot][0]);
            #pragma unroll
            for (int k = 0; k < 3; k++) {
                const int i = tid + k * BLOCK;
                if (i < (ROWS * 5) / 4)                      // 640 float4
                    cp16(sb + (uint32_t)i * 16, src + i);
            }
            if (tid < ROWS / 4) {                            // 128 float4
                const float4* __restrict__ tsrc =
                    reinterpret_cast<const float4*>(tgt + tile * ROWS);
                cp16((uint32_t)__cvta_generic_to_shared(&s_t[slot][0]) +
                         (uint32_t)tid * 16,
                     tsrc + tid);
            }
        }
        cp_commit();
    };

    const long long t0 = blockIdx.x;
    #pragma unroll
    for (int k = 0; k < STAGES; k++)
        stage(k, t0 + (long long)k * step);

    int cnt = 0;
    for (long long t = t0; t < fulltiles; t += step, cnt++) {
        const int slot = cnt % STAGES;
        cp_wait<STAGES - 2>();   // current slot's group complete
        __syncthreads();         // smem visible; prev slot fully consumed by all

        if (cnt > 0) {           // refill the slot consumed last iteration
            const int prev = (slot + STAGES - 1) % STAGES;
            stage(prev, t + (long long)(STAGES - 1) * step);
        }

        #pragma unroll
        for (int j = 0; j < ROWS / BLOCK; j++) {
            const int r = tid + j * BLOCK;
            const float x0 = s_in[slot][r * 5 + 0];
            const float x2 = s_in[slot][r * 5 + 2];
            const float x4 = s_in[slot][r * 5 + 4];
            const float tv = s_t[slot][r];
            const float d  = (fabsf(x4 - x2) < 0.1f) ? (x0 - x4) : (x0 - tv);
            acc += fabsf(d);
        }
    }
    cp_wait<0>();
    __syncthreads();

    // Block reduction (reuse s_t[0] as scratch — pipeline drained).
    #pragma unroll
    for (int off = 16; off > 0; off >>= 1)
        acc += __shfl_down_sync(0xFFFFFFFFu, acc, off);
    if ((tid & 31) == 0) s_t[0][tid >> 5] = acc;
    __syncthreads();

    __shared__ int s_last;
    if (tid == 0) {
        float v = 0.0f;
        #pragma unroll
        for (int w = 0; w < BLOCK / 32; w++) v += s_t[0][w];
        g_partials[blockIdx.x] = v;
        __threadfence();
        const unsigned int old = atomicAdd(&g_count, 1u);
        s_last = (old == gridDim.x - 1);
    }
    __syncthreads();

    // Last block: deterministic double-precision final reduce.
    if (s_last) {
        double* sd = reinterpret_cast<double*>(&s_in[0][0]);  // 16B-aligned
        double a = 0.0;
        for (int i = tid; i < NBLOCKS; i += BLOCK)
            a += (double)g_partials[i];
        #pragma unroll
        for (int off = 16; off > 0; off >>= 1)
            a += __shfl_down_sync(0xFFFFFFFFu, a, off);
        if ((tid & 31) == 0) sd[tid >> 5] = a;
        __syncthreads();
        if (tid == 0) {
            double s = 0.0;
            #pragma unroll
            for (int w = 0; w < BLOCK / 32; w++) s += sd[w];
            out[0] = (float)(s / (double)nrows);
            g_count = 0;    // reset for next graph replay (determinism)
        }
    }
}

extern "C" void kernel_launch(void* const* d_in, const int* in_sizes, int n_in,
                              void* d_out, int out_size)
{
    const float* inputs  = (const float*)d_in[0];   // [N, 5] fp32
    const float* targets = (const float*)d_in[1];   // [N, 1] fp32
    float* out = (float*)d_out;

    const long long nrows = (long long)in_sizes[0] / 5;

    loss_kernel<<<NBLOCKS, BLOCK>>>(inputs, targets, nrows, out);
}

// round 8
// speedup vs baseline: 1.1085x; 1.0004x over previous
#include <cuda_runtime.h>
#include <cstdint>

#define BLOCK   256
#define ROWS    512            // rows per tile; 2560 floats input + 512 targets
#define STAGES  3
#define NBLOCKS 888            // 148 SMs * 6 blocks (36KB smem each)

__device__ float g_partials[NBLOCKS];
__device__ unsigned int g_count = 0;

__device__ __forceinline__ void cp16(uint32_t smem_addr, const void* gptr) {
    asm volatile("cp.async.cg.shared.global [%0], [%1], 16;"
                 :: "r"(smem_addr), "l"(gptr));
}
__device__ __forceinline__ void cp_commit() {
    asm volatile("cp.async.commit_group;");
}
template <int N>
__device__ __forceinline__ void cp_wait() {
    asm volatile("cp.async.wait_group %0;" :: "n"(N));
}

__global__ void __launch_bounds__(BLOCK)
loss_kernel(const float* __restrict__ in,
            const float* __restrict__ tgt,
            long long nrows,
            float* __restrict__ out)
{
    __shared__ __align__(16) float s_in[STAGES][ROWS * 5];
    __shared__ __align__(16) float s_t[STAGES][ROWS];

    const int tid = threadIdx.x;
    const long long fulltiles = nrows / ROWS;
    const long long step = gridDim.x;
    float acc = 0.0f;

    // Tail rows (nrows % ROWS) handled by block 0 directly.
    if (blockIdx.x == 0) {
        for (long long r = fulltiles * ROWS + tid; r < nrows; r += BLOCK) {
            const float x0 = in[r * 5 + 0];
            const float x2 = in[r * 5 + 2];
            const float x4 = in[r * 5 + 4];
            const float t  = tgt[r];
            const float d  = (fabsf(x4 - x2) < 0.1f) ? (x0 - x4) : (x0 - t);
            acc += fabsf(d);
        }
    }

    auto stage = [&](int slot, long long tile) {
        if (tile < fulltiles) {
            const float4* __restrict__ src =
                reinterpret_cast<const float4*>(in + tile * (long long)ROWS * 5);
            const uint32_t sb = (uint32_t)__cvta_generic_to_shared(&s_in[slot][0]);
            #pragma unroll
            for (int k = 0; k < 3; k++) {
                const int i = tid + k * BLOCK;
                if (i < (ROWS * 5) / 4)                      // 640 float4
                    cp16(sb + (uint32_t)i * 16, src + i);
            }
            if (tid < ROWS / 4) {                            // 128 float4
                const float4* __restrict__ tsrc =
                    reinterpret_cast<const float4*>(tgt + tile * ROWS);
                cp16((uint32_t)__cvta_generic_to_shared(&s_t[slot][0]) +
                         (uint32_t)tid * 16,
                     tsrc + tid);
            }
        }
        cp_commit();
    };

    const long long t0 = blockIdx.x;
    #pragma unroll
    for (int k = 0; k < STAGES; k++)
        stage(k, t0 + (long long)k * step);

    int cnt = 0;
    for (long long t = t0; t < fulltiles; t += step, cnt++) {
        const int slot = cnt % STAGES;
        cp_wait<STAGES - 2>();   // current slot's group complete
        __syncthreads();         // smem visible; prev slot fully consumed by all

        if (cnt > 0) {           // refill the slot consumed last iteration
            const int prev = (slot + STAGES - 1) % STAGES;
            stage(prev, t + (long long)(STAGES - 1) * step);
        }

        #pragma unroll
        for (int j = 0; j < ROWS / BLOCK; j++) {
            const int r = tid + j * BLOCK;
            const float x0 = s_in[slot][r * 5 + 0];
            const float x2 = s_in[slot][r * 5 + 2];
            const float x4 = s_in[slot][r * 5 + 4];
            const float tv = s_t[slot][r];
            const float d  = (fabsf(x4 - x2) < 0.1f) ? (x0 - x4) : (x0 - tv);
            acc += fabsf(d);
        }
    }
    cp_wait<0>();
    __syncthreads();

    // Block reduction (reuse s_t[0] as scratch — pipeline drained).
    #pragma unroll
    for (int off = 16; off > 0; off >>= 1)
        acc += __shfl_down_sync(0xFFFFFFFFu, acc, off);
    if ((tid & 31) == 0) s_t[0][tid >> 5] = acc;
    __syncthreads();

    __shared__ int s_last;
    if (tid == 0) {
        float v = 0.0f;
        #pragma unroll
        for (int w = 0; w < BLOCK / 32; w++) v += s_t[0][w];
        g_partials[blockIdx.x] = v;
        __threadfence();
        const unsigned int old = atomicAdd(&g_count, 1u);
        s_last = (old == gridDim.x - 1);
    }
    __syncthreads();

    // Last block: deterministic double-precision final reduce.
    if (s_last) {
        double* sd = reinterpret_cast<double*>(&s_in[0][0]);  // 16B-aligned
        double a = 0.0;
        for (int i = tid; i < NBLOCKS; i += BLOCK)
            a += (double)g_partials[i];
        #pragma unroll
        for (int off = 16; off > 0; off >>= 1)
            a += __shfl_down_sync(0xFFFFFFFFu, a, off);
        if ((tid & 31) == 0) sd[tid >> 5] = a;
        __syncthreads();
        if (tid == 0) {
            double s = 0.0;
            #pragma unroll
            for (int w = 0; w < BLOCK / 32; w++) s += sd[w];
            out[0] = (float)(s / (double)nrows);
            g_count = 0;    // reset for next graph replay (determinism)
        }
    }
}

extern "C" void kernel_launch(void* const* d_in, const int* in_sizes, int n_in,
                              void* d_out, int out_size)
{
    const float* inputs  = (const float*)d_in[0];   // [N, 5] fp32
    const float* targets = (const float*)d_in[1];   // [N, 1] fp32
    float* out = (float*)d_out;

    const long long nrows = (long long)in_sizes[0] / 5;

    loss_kernel<<<NBLOCKS, BLOCK>>>(inputs, targets, nrows, out);
}